// round 10
// baseline (speedup 1.0000x reference)
#include <cuda_runtime.h>
#include <cuda_bf16.h>
#include <stdint.h>
#include <math.h>

// Problem constants (fixed by the dataset)
#define NN 100000
#define EE 1600000

// Scratch (allocation-free rule: static __device__ globals).
__device__ __align__(256) float          g_dinv[NN];
__device__ __align__(256) int            g_deg[NN];
__device__ __align__(256) int            g_rowstart[NN];
__device__ __align__(256) int            g_cursor[NN];
__device__ __align__(256) int            g_csr_src[EE];
__device__ __align__(256) float          g_csr_w[EE];
__device__ __align__(256) float          g_buf1[NN * 128];  // GEMM out (fp32)
__device__ __align__(256) float          g_buf2[NN * 128];  // agg out (fp32)
__device__ __align__(256) __nv_bfloat16  g_hhi[NN * 128];   // current input, hi part
__device__ __align__(256) __nv_bfloat16  g_hlo[NN * 128];   // current input, lo part
__device__ __align__(256) __nv_bfloat16  g_chi[NN * 32];    // cond hi
__device__ __align__(256) __nv_bfloat16  g_clo[NN * 32];    // cond lo
__device__ __align__(256) __nv_bfloat16  g_whi[160 * 128];  // weight hi (per layer)
__device__ __align__(256) __nv_bfloat16  g_wlo[160 * 128];  // weight lo (per layer)
__device__ int g_gcur;

static inline int cdiv(int a, int b) { return (a + b - 1) / b; }

__device__ __forceinline__ void split_bf16(float x, __nv_bfloat16& h, __nv_bfloat16& l) {
    h = __float2bfloat16_rn(x);
    l = __float2bfloat16_rn(x - __bfloat162float(h));
}

// ---------------------------------------------------------------------------
// fp32 -> (hi, lo) bf16 split (vectorized). n % 4 == 0.
// ---------------------------------------------------------------------------
__global__ void split_f32(const float* __restrict__ x,
                          __nv_bfloat16* __restrict__ hi,
                          __nv_bfloat16* __restrict__ lo, int n4) {
    int t = blockIdx.x * blockDim.x + threadIdx.x;
    if (t >= n4) return;
    float4 v = ((const float4*)x)[t];
    __nv_bfloat16 h0, h1, h2, h3, l0, l1, l2, l3;
    split_bf16(v.x, h0, l0); split_bf16(v.y, h1, l1);
    split_bf16(v.z, h2, l2); split_bf16(v.w, h3, l3);
    ((__nv_bfloat162*)hi)[t * 2 + 0] = __nv_bfloat162(h0, h1);
    ((__nv_bfloat162*)hi)[t * 2 + 1] = __nv_bfloat162(h2, h3);
    ((__nv_bfloat162*)lo)[t * 2 + 0] = __nv_bfloat162(l0, l1);
    ((__nv_bfloat162*)lo)[t * 2 + 1] = __nv_bfloat162(l2, l3);
}

// ---------------------------------------------------------------------------
// CSR construction (edge_index is int32)
// ---------------------------------------------------------------------------
__global__ void reset_counters(int* deg, int* gcur, int n) {
    int i = blockIdx.x * blockDim.x + threadIdx.x;
    if (i < n) deg[i] = 0;
    if (i == 0) *gcur = 0;
}

__global__ void deg_count(const int* __restrict__ dst, int* __restrict__ deg, int E) {
    int i = blockIdx.x * blockDim.x + threadIdx.x;
    if (i < E) atomicAdd(&deg[dst[i]], 1);
}

__global__ void dinv_compute(const int* __restrict__ deg, float* __restrict__ dinv, int n) {
    int i = blockIdx.x * blockDim.x + threadIdx.x;
    if (i < n) dinv[i] = rsqrtf((float)deg[i] + 1.0f);
}

__global__ void assign_rows(const int* __restrict__ deg, int* __restrict__ rowstart,
                            int* __restrict__ cursor, int* gcur, int n) {
    int i = blockIdx.x * blockDim.x + threadIdx.x;
    int lane = threadIdx.x & 31;
    int d = (i < n) ? deg[i] : 0;
    int incl = d;
#pragma unroll
    for (int o = 1; o < 32; o <<= 1) {
        int v = __shfl_up_sync(0xFFFFFFFFu, incl, o);
        if (lane >= o) incl += v;
    }
    int total = __shfl_sync(0xFFFFFFFFu, incl, 31);
    int base = 0;
    if (lane == 31) base = atomicAdd(gcur, total);
    base = __shfl_sync(0xFFFFFFFFu, base, 31);
    int excl = incl - d;
    if (i < n) {
        rowstart[i] = base + excl;
        cursor[i]   = base + excl;
    }
}

__global__ void csr_fill(const int* __restrict__ src, const int* __restrict__ dst,
                         const float* __restrict__ dinv,
                         int* __restrict__ cursor,
                         int* __restrict__ csr_src, float* __restrict__ csr_w, int E) {
    int i = blockIdx.x * blockDim.x + threadIdx.x;
    if (i >= E) return;
    int s = src[i];
    int d = dst[i];
    int pos = atomicAdd(&cursor[d], 1);
    csr_src[pos] = s;
    csr_w[pos] = dinv[s] * dinv[d];
}

// ---------------------------------------------------------------------------
// bf16-split tensor-core GEMM on pre-split inputs, register-pipelined.
// out[M, Nout] = concat(xA[:,0:KA], xB[:,0:KB]) @ W[K, Nout]
// via A_hi*B_hi + A_hi*B_lo + A_lo*B_hi, fp32 accum.
// BM=128, BK=32, 256 threads (8 warps, 4x2). KA % 32 == 0.
// ---------------------------------------------------------------------------
__device__ __forceinline__ void ldsm_x4(uint32_t a, uint32_t& r0, uint32_t& r1,
                                        uint32_t& r2, uint32_t& r3) {
    asm volatile("ldmatrix.sync.aligned.m8n8.x4.shared.b16 {%0,%1,%2,%3}, [%4];"
                 : "=r"(r0), "=r"(r1), "=r"(r2), "=r"(r3) : "r"(a));
}
__device__ __forceinline__ void ldsm_x4_t(uint32_t a, uint32_t& r0, uint32_t& r1,
                                          uint32_t& r2, uint32_t& r3) {
    asm volatile("ldmatrix.sync.aligned.m8n8.x4.trans.shared.b16 {%0,%1,%2,%3}, [%4];"
                 : "=r"(r0), "=r"(r1), "=r"(r2), "=r"(r3) : "r"(a));
}
__device__ __forceinline__ void mma_bf16(float* c, const uint32_t* a, const uint32_t* b) {
    asm volatile(
        "mma.sync.aligned.m16n8k16.row.col.f32.bf16.bf16.f32 "
        "{%0,%1,%2,%3}, {%4,%5,%6,%7}, {%8,%9}, {%0,%1,%2,%3};"
        : "+f"(c[0]), "+f"(c[1]), "+f"(c[2]), "+f"(c[3])
        : "r"(a[0]), "r"(a[1]), "r"(a[2]), "r"(a[3]), "r"(b[0]), "r"(b[1]));
}

template <int BN>
__global__ __launch_bounds__(256)
void gemm_bf16(const __nv_bfloat16* __restrict__ xAhi,
               const __nv_bfloat16* __restrict__ xAlo, int KA,
               const __nv_bfloat16* __restrict__ xBhi,
               const __nv_bfloat16* __restrict__ xBlo, int KB,
               const __nv_bfloat16* __restrict__ Wgh,
               const __nv_bfloat16* __restrict__ Wgl,
               float* __restrict__ out, int M, int Nout) {
    constexpr int BM = 128, BK = 32;
    constexpr int XS = BK + 8;               // X smem row stride (bf16), 80 B
    constexpr int WS = BN + 8;               // W smem row stride
    constexpr int WN = BN / 2;
    constexpr int NT = WN / 8;
    constexpr int MT = 2;
    constexpr int CX = 2;                    // X 16B chunks per thread
    constexpr int CW = (BK * BN / 8) / 256;  // W 16B chunks per thread (2 or 1)

    __shared__ __nv_bfloat16 Xhi[BM * XS], Xlo[BM * XS];
    __shared__ __nv_bfloat16 Whs[BK * WS], Wls[BK * WS];

    const int K = KA + KB;
    const int nIter = K / BK;
    const int tid = threadIdx.x;
    const int warp = tid >> 5;
    const int lane = tid & 31;
    const int warp_m = warp >> 1;
    const int warp_n = warp & 1;
    const int rowBase = blockIdx.y * BM;

    float acc[MT][NT][4];
#pragma unroll
    for (int i = 0; i < MT; i++)
#pragma unroll
        for (int j = 0; j < NT; j++)
#pragma unroll
            for (int q = 0; q < 4; q++) acc[i][j][q] = 0.0f;

    const uint32_t xhi_b = (uint32_t)__cvta_generic_to_shared(Xhi);
    const uint32_t xlo_b = (uint32_t)__cvta_generic_to_shared(Xlo);
    const uint32_t whi_b = (uint32_t)__cvta_generic_to_shared(Whs);
    const uint32_t wlo_b = (uint32_t)__cvta_generic_to_shared(Wls);

    uint4 rxh[CX], rxl[CX], rwh[CW], rwl[CW];

    // ---- load tile `it` from global into registers ----
    auto load_tile = [&](int it) {
        int k0 = it * BK;
#pragma unroll
        for (int c = 0; c < CX; c++) {
            int chunk = tid + c * 256;       // 0..511
            int r = chunk >> 2;              // row in tile
            int ch = chunk & 3;              // 16B chunk along K
            int gr = rowBase + r;
            int kk = k0 + ch * 8;
            rxh[c] = make_uint4(0, 0, 0, 0);
            rxl[c] = make_uint4(0, 0, 0, 0);
            if (gr < M) {
                if (kk < KA) {
                    rxh[c] = *(const uint4*)(xAhi + (size_t)gr * KA + kk);
                    rxl[c] = *(const uint4*)(xAlo + (size_t)gr * KA + kk);
                } else {
                    rxh[c] = *(const uint4*)(xBhi + (size_t)gr * KB + (kk - KA));
                    rxl[c] = *(const uint4*)(xBlo + (size_t)gr * KB + (kk - KA));
                }
            }
        }
#pragma unroll
        for (int c = 0; c < CW; c++) {
            int chunk = tid + c * 256;
            int kr = chunk / (BN / 8);
            int nc = chunk % (BN / 8);
            rwh[c] = *(const uint4*)(Wgh + (size_t)(k0 + kr) * Nout + nc * 8);
            rwl[c] = *(const uint4*)(Wgl + (size_t)(k0 + kr) * Nout + nc * 8);
        }
    };
    // ---- store staged registers to smem ----
    auto store_tile = [&]() {
#pragma unroll
        for (int c = 0; c < CX; c++) {
            int chunk = tid + c * 256;
            int r = chunk >> 2;
            int ch = chunk & 3;
            *(uint4*)&Xhi[r * XS + ch * 8] = rxh[c];
            *(uint4*)&Xlo[r * XS + ch * 8] = rxl[c];
        }
#pragma unroll
        for (int c = 0; c < CW; c++) {
            int chunk = tid + c * 256;
            int kr = chunk / (BN / 8);
            int nc = chunk % (BN / 8);
            *(uint4*)&Whs[kr * WS + nc * 8] = rwh[c];
            *(uint4*)&Wls[kr * WS + nc * 8] = rwl[c];
        }
    };
    // ---- MMA on current smem tile ----
    auto compute_tile = [&]() {
#pragma unroll
        for (int ks = 0; ks < BK / 16; ks++) {
            uint32_t ahi[MT][4];
            uint32_t alo[MT][4];
#pragma unroll
            for (int mt = 0; mt < MT; mt++) {
                int r = warp_m * 32 + mt * 16 + (lane & 15);
                int c = ks * 16 + (lane >> 4) * 8;
                uint32_t off = (uint32_t)(r * XS + c) * 2;
                ldsm_x4(xhi_b + off, ahi[mt][0], ahi[mt][1], ahi[mt][2], ahi[mt][3]);
                ldsm_x4(xlo_b + off, alo[mt][0], alo[mt][1], alo[mt][2], alo[mt][3]);
            }
            uint32_t bhi[NT][2];
            uint32_t blo[NT][2];
#pragma unroll
            for (int np = 0; np < NT / 2; np++) {
                int r = ks * 16 + (lane & 15);
                int c = warp_n * WN + np * 16 + (lane >> 4) * 8;
                uint32_t off = (uint32_t)(r * WS + c) * 2;
                ldsm_x4_t(whi_b + off, bhi[2 * np][0], bhi[2 * np][1],
                          bhi[2 * np + 1][0], bhi[2 * np + 1][1]);
                ldsm_x4_t(wlo_b + off, blo[2 * np][0], blo[2 * np][1],
                          blo[2 * np + 1][0], blo[2 * np + 1][1]);
            }
#pragma unroll
            for (int mt = 0; mt < MT; mt++)
#pragma unroll
                for (int nt = 0; nt < NT; nt++) {
                    mma_bf16(acc[mt][nt], ahi[mt], bhi[nt]);
                    mma_bf16(acc[mt][nt], ahi[mt], blo[nt]);
                    mma_bf16(acc[mt][nt], alo[mt], bhi[nt]);
                }
        }
    };

    // ---- pipelined mainloop ----
    load_tile(0);
    store_tile();
    __syncthreads();
    for (int it = 0;;) {
        bool has_next = (it + 1 < nIter);
        if (has_next) load_tile(it + 1);   // LDGs in flight during compute
        compute_tile();
        ++it;
        if (!has_next) break;
        __syncthreads();                   // everyone done reading smem
        store_tile();
        __syncthreads();
    }

    // ---- store fp32 ----
#pragma unroll
    for (int mt = 0; mt < MT; mt++) {
#pragma unroll
        for (int nt = 0; nt < NT; nt++) {
            int row = rowBase + warp_m * 32 + mt * 16 + (lane >> 2);
            int col = warp_n * WN + nt * 8 + (lane & 3) * 2;
            if (row < M)
                *(float2*)(out + (size_t)row * Nout + col) =
                    make_float2(acc[mt][nt][0], acc[mt][nt][1]);
            if (row + 8 < M)
                *(float2*)(out + (size_t)(row + 8) * Nout + col) =
                    make_float2(acc[mt][nt][2], acc[mt][nt][3]);
        }
    }
}

// ---------------------------------------------------------------------------
// Fused aggregation: out[d] = act( dinv[d]^2*H[d] + sum_e w[e]*H[src[e]] + b )
// One warp per node, fp32 gathers, no atomics. Optionally writes bf16 hi/lo
// shadows of the result (inputs of the next GEMM).
// ---------------------------------------------------------------------------
template <int F, int ACT, int WSPLIT>
__global__ void agg_fused(const float* __restrict__ H,
                          const int* __restrict__ rowstart,
                          const int* __restrict__ deg,
                          const int* __restrict__ csr_src,
                          const float* __restrict__ csr_w,
                          const float* __restrict__ dinv,
                          const float* __restrict__ bias,
                          float* __restrict__ out,
                          __nv_bfloat16* __restrict__ ohi,
                          __nv_bfloat16* __restrict__ olo, int M) {
    constexpr int V = F / 32;
    int warp = (blockIdx.x * blockDim.x + threadIdx.x) >> 5;
    if (warp >= M) return;
    int lane = threadIdx.x & 31;

    float acc[V];
    {
        float dv = dinv[warp];
        float s = dv * dv;
        if (V == 4) {
            float4 v = *(const float4*)(H + (size_t)warp * F + lane * 4);
            acc[0] = s * v.x; acc[1] = s * v.y; acc[2] = s * v.z; acc[3] = s * v.w;
        } else {
            float2 v = *(const float2*)(H + (size_t)warp * F + lane * 2);
            acc[0] = s * v.x; acc[1] = s * v.y;
        }
    }

    int beg = rowstart[warp];
    int n = deg[warp];
    int j = 0;
    for (; j + 2 <= n; j += 2) {
        int s0 = csr_src[beg + j];
        int s1 = csr_src[beg + j + 1];
        float w0 = csr_w[beg + j];
        float w1 = csr_w[beg + j + 1];
        if (V == 4) {
            float4 v0 = *(const float4*)(H + (size_t)s0 * F + lane * 4);
            float4 v1 = *(const float4*)(H + (size_t)s1 * F + lane * 4);
            acc[0] = fmaf(w0, v0.x, acc[0]); acc[1] = fmaf(w0, v0.y, acc[1]);
            acc[2] = fmaf(w0, v0.z, acc[2]); acc[3] = fmaf(w0, v0.w, acc[3]);
            acc[0] = fmaf(w1, v1.x, acc[0]); acc[1] = fmaf(w1, v1.y, acc[1]);
            acc[2] = fmaf(w1, v1.z, acc[2]); acc[3] = fmaf(w1, v1.w, acc[3]);
        } else {
            float2 v0 = *(const float2*)(H + (size_t)s0 * F + lane * 2);
            float2 v1 = *(const float2*)(H + (size_t)s1 * F + lane * 2);
            acc[0] = fmaf(w0, v0.x, acc[0]); acc[1] = fmaf(w0, v0.y, acc[1]);
            acc[0] = fmaf(w1, v1.x, acc[0]); acc[1] = fmaf(w1, v1.y, acc[1]);
        }
    }
    if (j < n) {
        int s0 = csr_src[beg + j];
        float w0 = csr_w[beg + j];
        if (V == 4) {
            float4 v0 = *(const float4*)(H + (size_t)s0 * F + lane * 4);
            acc[0] = fmaf(w0, v0.x, acc[0]); acc[1] = fmaf(w0, v0.y, acc[1]);
            acc[2] = fmaf(w0, v0.z, acc[2]); acc[3] = fmaf(w0, v0.w, acc[3]);
        } else {
            float2 v0 = *(const float2*)(H + (size_t)s0 * F + lane * 2);
            acc[0] = fmaf(w0, v0.x, acc[0]); acc[1] = fmaf(w0, v0.y, acc[1]);
        }
    }

    if (V == 4) {
        float4 b = *(const float4*)(bias + lane * 4);
        acc[0] += b.x; acc[1] += b.y; acc[2] += b.z; acc[3] += b.w;
        if (ACT) {
            acc[0] = tanhf(acc[0]); acc[1] = tanhf(acc[1]);
            acc[2] = tanhf(acc[2]); acc[3] = tanhf(acc[3]);
        }
        *(float4*)(out + (size_t)warp * F + lane * 4) =
            make_float4(acc[0], acc[1], acc[2], acc[3]);
    } else {
        float2 b = *(const float2*)(bias + lane * 2);
        acc[0] += b.x; acc[1] += b.y;
        if (ACT) { acc[0] = tanhf(acc[0]); acc[1] = tanhf(acc[1]); }
        *(float2*)(out + (size_t)warp * F + lane * 2) = make_float2(acc[0], acc[1]);
    }

    if (WSPLIT) {
        __nv_bfloat16 h[V], l[V];
#pragma unroll
        for (int q = 0; q < V; q++) split_bf16(acc[q], h[q], l[q]);
        if (V == 4) {
            size_t o = (size_t)warp * F + lane * 4;
            *(__nv_bfloat162*)(ohi + o)     = __nv_bfloat162(h[0], h[1]);
            *(__nv_bfloat162*)(ohi + o + 2) = __nv_bfloat162(h[2], h[3]);
            *(__nv_bfloat162*)(olo + o)     = __nv_bfloat162(l[0], l[1]);
            *(__nv_bfloat162*)(olo + o + 2) = __nv_bfloat162(l[2], l[3]);
        } else {
            size_t o = (size_t)warp * F + lane * 2;
            *(__nv_bfloat162*)(ohi + o) = __nv_bfloat162(h[0], h[1]);
            *(__nv_bfloat162*)(olo + o) = __nv_bfloat162(l[0], l[1]);
        }
    }
}

// ---------------------------------------------------------------------------
// Host side
// ---------------------------------------------------------------------------
extern "C" void kernel_launch(void* const* d_in, const int* in_sizes, int n_in,
                              void* d_out, int out_size) {
    const float* feat = (const float*)d_in[0];   // [N,128] f32
    const float* cond = (const float*)d_in[1];   // [N,32]  f32
    const int*   ei   = (const int*)d_in[2];     // [2,E] int32
    const float* We1 = (const float*)d_in[3];
    const float* be1 = (const float*)d_in[4];
    const float* We2 = (const float*)d_in[5];
    const float* be2 = (const float*)d_in[6];
    const float* We3 = (const float*)d_in[7];
    const float* be3 = (const float*)d_in[8];
    const float* Wd1 = (const float*)d_in[9];
    const float* bd1 = (const float*)d_in[10];
    const float* Wd2 = (const float*)d_in[11];
    const float* bd2 = (const float*)d_in[12];
    const float* Wd3 = (const float*)d_in[13];
    const float* bd3 = (const float*)d_in[14];

    const int N = in_sizes[0] / 128;
    const int E = in_sizes[2] / 2;
    const int* src = ei;
    const int* dst = ei + E;
    float* out = (float*)d_out;

    float *dinv, *buf1, *buf2, *csr_w;
    __nv_bfloat16 *hhi, *hlo, *chi, *clo, *whi, *wlo;
    int *deg, *rowstart, *cursor, *csr_src, *gcur;
    cudaGetSymbolAddress((void**)&dinv, g_dinv);
    cudaGetSymbolAddress((void**)&deg, g_deg);
    cudaGetSymbolAddress((void**)&rowstart, g_rowstart);
    cudaGetSymbolAddress((void**)&cursor, g_cursor);
    cudaGetSymbolAddress((void**)&csr_src, g_csr_src);
    cudaGetSymbolAddress((void**)&csr_w, g_csr_w);
    cudaGetSymbolAddress((void**)&buf1, g_buf1);
    cudaGetSymbolAddress((void**)&buf2, g_buf2);
    cudaGetSymbolAddress((void**)&hhi, g_hhi);
    cudaGetSymbolAddress((void**)&hlo, g_hlo);
    cudaGetSymbolAddress((void**)&chi, g_chi);
    cudaGetSymbolAddress((void**)&clo, g_clo);
    cudaGetSymbolAddress((void**)&whi, g_whi);
    cudaGetSymbolAddress((void**)&wlo, g_wlo);
    cudaGetSymbolAddress((void**)&gcur, g_gcur);

    // ---- input splits + CSR build (once per launch) ----
    split_f32<<<cdiv(N * 32, 256), 256>>>(feat, hhi, hlo, N * 32);   // N*128/4
    split_f32<<<cdiv(N * 8, 256), 256>>>(cond, chi, clo, N * 8);     // N*32/4
    reset_counters<<<cdiv(N, 256), 256>>>(deg, gcur, N);
    deg_count<<<cdiv(E, 256), 256>>>(dst, deg, E);
    dinv_compute<<<cdiv(N, 256), 256>>>(deg, dinv, N);
    assign_rows<<<cdiv(N, 256), 256>>>(deg, rowstart, cursor, gcur, N);
    csr_fill<<<cdiv(E, 256), 256>>>(src, dst, dinv, cursor, csr_src, csr_w, E);

    dim3 gB(1, cdiv(N, 128));
    const int aggBlocks = cdiv(N * 32, 256);

    // encoder layer 1: [feat|cond] (K=160) -> 128, tanh
    split_f32<<<cdiv(160 * 32, 256), 256>>>(We1, whi, wlo, 160 * 32);
    gemm_bf16<128><<<gB, 256>>>(hhi, hlo, 128, chi, clo, 32, whi, wlo, buf1, N, 128);
    agg_fused<128, 1, 1><<<aggBlocks, 256>>>(buf1, rowstart, deg, csr_src, csr_w,
                                             dinv, be1, buf2, hhi, hlo, N);

    // encoder layer 2: 128 -> 128, tanh
    split_f32<<<cdiv(128 * 32, 256), 256>>>(We2, whi, wlo, 128 * 32);
    gemm_bf16<128><<<gB, 256>>>(hhi, hlo, 128, nullptr, nullptr, 0, whi, wlo, buf1, N, 128);
    agg_fused<128, 1, 1><<<aggBlocks, 256>>>(buf1, rowstart, deg, csr_src, csr_w,
                                             dinv, be2, buf2, hhi, hlo, N);

    // encoder layer 3: 128 -> 64 (z), no activation
    split_f32<<<cdiv(128 * 16, 256), 256>>>(We3, whi, wlo, 128 * 16);
    gemm_bf16<64><<<gB, 256>>>(hhi, hlo, 128, nullptr, nullptr, 0, whi, wlo, buf1, N, 64);
    agg_fused<64, 0, 1><<<aggBlocks, 256>>>(buf1, rowstart, deg, csr_src, csr_w,
                                            dinv, be3, buf2, hhi, hlo, N);  // z [N,64]

    // decoder layer 1: [z|cond] (K=96) -> 128, tanh
    split_f32<<<cdiv(96 * 32, 256), 256>>>(Wd1, whi, wlo, 96 * 32);
    gemm_bf16<128><<<gB, 256>>>(hhi, hlo, 64, chi, clo, 32, whi, wlo, buf1, N, 128);
    agg_fused<128, 1, 1><<<aggBlocks, 256>>>(buf1, rowstart, deg, csr_src, csr_w,
                                             dinv, bd1, buf2, hhi, hlo, N);

    // decoder layer 2: 128 -> 128, tanh
    split_f32<<<cdiv(128 * 32, 256), 256>>>(Wd2, whi, wlo, 128 * 32);
    gemm_bf16<128><<<gB, 256>>>(hhi, hlo, 128, nullptr, nullptr, 0, whi, wlo, buf1, N, 128);
    agg_fused<128, 1, 1><<<aggBlocks, 256>>>(buf1, rowstart, deg, csr_src, csr_w,
                                             dinv, bd2, buf2, hhi, hlo, N);

    // decoder layer 3: 128 -> 128, no activation, write to d_out
    split_f32<<<cdiv(128 * 32, 256), 256>>>(Wd3, whi, wlo, 128 * 32);
    gemm_bf16<128><<<gB, 256>>>(hhi, hlo, 128, nullptr, nullptr, 0, whi, wlo, buf1, N, 128);
    agg_fused<128, 0, 0><<<aggBlocks, 256>>>(buf1, rowstart, deg, csr_src, csr_w,
                                             dinv, bd3, out, nullptr, nullptr, N);
}

// round 12
// speedup vs baseline: 1.1762x; 1.1762x over previous
#include <cuda_runtime.h>
#include <cuda_bf16.h>
#include <stdint.h>
#include <math.h>

// Problem constants (fixed by the dataset)
#define NN 100000
#define EE 1600000

// Scratch (allocation-free rule: static __device__ globals).
__device__ __align__(256) float          g_dinv[NN];
__device__ __align__(256) int            g_deg[NN];
__device__ __align__(256) int            g_rowstart[NN];
__device__ __align__(256) int            g_cursor[NN];
__device__ __align__(256) int            g_csr_src[EE];
__device__ __align__(256) float          g_csr_w[EE];
__device__ __align__(256) float          g_buf1[NN * 128];  // GEMM out (fp32)
__device__ __align__(256) __nv_bfloat16  g_fhi[NN * 128];   // feat hi
__device__ __align__(256) __nv_bfloat16  g_flo[NN * 128];   // feat lo
__device__ __align__(256) __nv_bfloat16  g_hhi[NN * 128];   // layer activation hi
__device__ __align__(256) __nv_bfloat16  g_hlo[NN * 128];   // layer activation lo
__device__ __align__(256) __nv_bfloat16  g_chi[NN * 32];    // cond hi
__device__ __align__(256) __nv_bfloat16  g_clo[NN * 32];    // cond lo
__device__ __align__(256) __nv_bfloat16  g_w1h[160 * 128], g_w1l[160 * 128];
__device__ __align__(256) __nv_bfloat16  g_w2h[128 * 128], g_w2l[128 * 128];
__device__ __align__(256) __nv_bfloat16  g_w3h[128 * 64],  g_w3l[128 * 64];
__device__ __align__(256) __nv_bfloat16  g_w4h[96 * 128],  g_w4l[96 * 128];
__device__ __align__(256) __nv_bfloat16  g_w5h[128 * 128], g_w5l[128 * 128];
__device__ __align__(256) __nv_bfloat16  g_w6h[128 * 128], g_w6l[128 * 128];
__device__ int g_gcur;

// float4-chunk counts of the 6 weight matrices (MUST match split_all's S-chain)
#define W1Q (160 * 128 / 4)
#define W2Q (128 * 128 / 4)
#define W3Q (128 * 64 / 4)
#define W4Q (96 * 128 / 4)
#define W5Q (128 * 128 / 4)
#define W6Q (128 * 128 / 4)
#define WALLQ (W1Q + W2Q + W3Q + W4Q + W5Q + W6Q)   // 22528

static inline int cdiv(int a, int b) { return (a + b - 1) / b; }

__device__ __forceinline__ void split_bf16(float x, __nv_bfloat16& h, __nv_bfloat16& l) {
    h = __float2bfloat16_rn(x);
    l = __float2bfloat16_rn(x - __bfloat162float(h));
}

__device__ __forceinline__ void split4(const float* __restrict__ src,
                                       __nv_bfloat16* __restrict__ hi,
                                       __nv_bfloat16* __restrict__ lo, int t) {
    float4 v = ((const float4*)src)[t];
    __nv_bfloat16 h0, h1, h2, h3, l0, l1, l2, l3;
    split_bf16(v.x, h0, l0); split_bf16(v.y, h1, l1);
    split_bf16(v.z, h2, l2); split_bf16(v.w, h3, l3);
    ((__nv_bfloat162*)hi)[t * 2 + 0] = __nv_bfloat162(h0, h1);
    ((__nv_bfloat162*)hi)[t * 2 + 1] = __nv_bfloat162(h2, h3);
    ((__nv_bfloat162*)lo)[t * 2 + 0] = __nv_bfloat162(l0, l1);
    ((__nv_bfloat162*)lo)[t * 2 + 1] = __nv_bfloat162(l2, l3);
}

// ---------------------------------------------------------------------------
// One kernel: split feat/cond/all-6-weights to bf16 hi/lo + zero deg & gcur.
// Segments in float4 units.
// ---------------------------------------------------------------------------
__global__ void split_all(const float* feat, const float* cond,
                          const float* We1, const float* We2, const float* We3,
                          const float* Wd1, const float* Wd2, const float* Wd3,
                          __nv_bfloat16* fhi, __nv_bfloat16* flo,
                          __nv_bfloat16* chi, __nv_bfloat16* clo,
                          __nv_bfloat16* w1h, __nv_bfloat16* w1l,
                          __nv_bfloat16* w2h, __nv_bfloat16* w2l,
                          __nv_bfloat16* w3h, __nv_bfloat16* w3l,
                          __nv_bfloat16* w4h, __nv_bfloat16* w4l,
                          __nv_bfloat16* w5h, __nv_bfloat16* w5l,
                          __nv_bfloat16* w6h, __nv_bfloat16* w6l,
                          int* deg, int* gcur, int N) {
    const int S0 = N * 32;          // feat (N*128/4)
    const int S1 = S0 + N * 8;      // cond (N*32/4)
    const int S2 = S1 + W1Q;
    const int S3 = S2 + W2Q;
    const int S4 = S3 + W3Q;
    const int S5 = S4 + W4Q;
    const int S6 = S5 + W5Q;
    const int S7 = S6 + W6Q;
    const int S8 = S7 + N / 4;      // deg zero (int4)
    int t = blockIdx.x * blockDim.x + threadIdx.x;
    if (t < S0)      split4(feat, fhi, flo, t);
    else if (t < S1) split4(cond, chi, clo, t - S0);
    else if (t < S2) split4(We1, w1h, w1l, t - S1);
    else if (t < S3) split4(We2, w2h, w2l, t - S2);
    else if (t < S4) split4(We3, w3h, w3l, t - S3);
    else if (t < S5) split4(Wd1, w4h, w4l, t - S4);
    else if (t < S6) split4(Wd2, w5h, w5l, t - S5);
    else if (t < S7) split4(Wd3, w6h, w6l, t - S6);
    else if (t < S8) ((int4*)deg)[t - S7] = make_int4(0, 0, 0, 0);
    else if (t == S8) *gcur = 0;
}

// ---------------------------------------------------------------------------
// CSR construction (edge_index is int32)
// ---------------------------------------------------------------------------
__global__ void deg_count(const int* __restrict__ dst, int* __restrict__ deg, int E) {
    int i = blockIdx.x * blockDim.x + threadIdx.x;
    if (i < E) atomicAdd(&deg[dst[i]], 1);
}

// dinv + contiguous slice assignment (warp-aggregated scan), merged.
__global__ void dinv_assign(const int* __restrict__ deg, float* __restrict__ dinv,
                            int* __restrict__ rowstart, int* __restrict__ cursor,
                            int* gcur, int n) {
    int i = blockIdx.x * blockDim.x + threadIdx.x;
    int lane = threadIdx.x & 31;
    int d = (i < n) ? deg[i] : 0;
    if (i < n) dinv[i] = rsqrtf((float)d + 1.0f);
    int incl = d;
#pragma unroll
    for (int o = 1; o < 32; o <<= 1) {
        int v = __shfl_up_sync(0xFFFFFFFFu, incl, o);
        if (lane >= o) incl += v;
    }
    int total = __shfl_sync(0xFFFFFFFFu, incl, 31);
    int base = 0;
    if (lane == 31) base = atomicAdd(gcur, total);
    base = __shfl_sync(0xFFFFFFFFu, base, 31);
    int excl = incl - d;
    if (i < n) {
        rowstart[i] = base + excl;
        cursor[i]   = base + excl;
    }
}

__global__ void csr_fill(const int* __restrict__ src, const int* __restrict__ dst,
                         const float* __restrict__ dinv,
                         int* __restrict__ cursor,
                         int* __restrict__ csr_src, float* __restrict__ csr_w, int E) {
    int i = blockIdx.x * blockDim.x + threadIdx.x;
    if (i >= E) return;
    int s = src[i];
    int d = dst[i];
    int pos = atomicAdd(&cursor[d], 1);
    csr_src[pos] = s;
    csr_w[pos] = dinv[s] * dinv[d];
}

// ---------------------------------------------------------------------------
// bf16-split tensor-core GEMM on pre-split inputs, register-pipelined.
// out = concat(xA,xB) @ W via A_hi*B_hi + A_hi*B_lo + A_lo*B_hi, fp32 accum.
// BM=128, BK=32, 256 threads (8 warps, 4x2).
// ---------------------------------------------------------------------------
__device__ __forceinline__ void ldsm_x4(uint32_t a, uint32_t& r0, uint32_t& r1,
                                        uint32_t& r2, uint32_t& r3) {
    asm volatile("ldmatrix.sync.aligned.m8n8.x4.shared.b16 {%0,%1,%2,%3}, [%4];"
                 : "=r"(r0), "=r"(r1), "=r"(r2), "=r"(r3) : "r"(a));
}
__device__ __forceinline__ void ldsm_x4_t(uint32_t a, uint32_t& r0, uint32_t& r1,
                                          uint32_t& r2, uint32_t& r3) {
    asm volatile("ldmatrix.sync.aligned.m8n8.x4.trans.shared.b16 {%0,%1,%2,%3}, [%4];"
                 : "=r"(r0), "=r"(r1), "=r"(r2), "=r"(r3) : "r"(a));
}
__device__ __forceinline__ void mma_bf16(float* c, const uint32_t* a, const uint32_t* b) {
    asm volatile(
        "mma.sync.aligned.m16n8k16.row.col.f32.bf16.bf16.f32 "
        "{%0,%1,%2,%3}, {%4,%5,%6,%7}, {%8,%9}, {%0,%1,%2,%3};"
        : "+f"(c[0]), "+f"(c[1]), "+f"(c[2]), "+f"(c[3])
        : "r"(a[0]), "r"(a[1]), "r"(a[2]), "r"(a[3]), "r"(b[0]), "r"(b[1]));
}

template <int BN>
__global__ __launch_bounds__(256)
void gemm_bf16(const __nv_bfloat16* __restrict__ xAhi,
               const __nv_bfloat16* __restrict__ xAlo, int KA,
               const __nv_bfloat16* __restrict__ xBhi,
               const __nv_bfloat16* __restrict__ xBlo, int KB,
               const __nv_bfloat16* __restrict__ Wgh,
               const __nv_bfloat16* __restrict__ Wgl,
               float* __restrict__ out, int M, int Nout) {
    constexpr int BM = 128, BK = 32;
    constexpr int XS = BK + 8;
    constexpr int WS = BN + 8;
    constexpr int WN = BN / 2;
    constexpr int NT = WN / 8;
    constexpr int MT = 2;
    constexpr int CX = 2;
    constexpr int CW = (BK * BN / 8) / 256;

    __shared__ __nv_bfloat16 Xhi[BM * XS], Xlo[BM * XS];
    __shared__ __nv_bfloat16 Whs[BK * WS], Wls[BK * WS];

    const int K = KA + KB;
    const int nIter = K / BK;
    const int tid = threadIdx.x;
    const int warp = tid >> 5;
    const int lane = tid & 31;
    const int warp_m = warp >> 1;
    const int warp_n = warp & 1;
    const int rowBase = blockIdx.y * BM;

    float acc[MT][NT][4];
#pragma unroll
    for (int i = 0; i < MT; i++)
#pragma unroll
        for (int j = 0; j < NT; j++)
#pragma unroll
            for (int q = 0; q < 4; q++) acc[i][j][q] = 0.0f;

    const uint32_t xhi_b = (uint32_t)__cvta_generic_to_shared(Xhi);
    const uint32_t xlo_b = (uint32_t)__cvta_generic_to_shared(Xlo);
    const uint32_t whi_b = (uint32_t)__cvta_generic_to_shared(Whs);
    const uint32_t wlo_b = (uint32_t)__cvta_generic_to_shared(Wls);

    uint4 rxh[CX], rxl[CX], rwh[CW], rwl[CW];

    auto load_tile = [&](int it) {
        int k0 = it * BK;
#pragma unroll
        for (int c = 0; c < CX; c++) {
            int chunk = tid + c * 256;
            int r = chunk >> 2;
            int ch = chunk & 3;
            int gr = rowBase + r;
            int kk = k0 + ch * 8;
            rxh[c] = make_uint4(0, 0, 0, 0);
            rxl[c] = make_uint4(0, 0, 0, 0);
            if (gr < M) {
                if (kk < KA) {
                    rxh[c] = *(const uint4*)(xAhi + (size_t)gr * KA + kk);
                    rxl[c] = *(const uint4*)(xAlo + (size_t)gr * KA + kk);
                } else {
                    rxh[c] = *(const uint4*)(xBhi + (size_t)gr * KB + (kk - KA));
                    rxl[c] = *(const uint4*)(xBlo + (size_t)gr * KB + (kk - KA));
                }
            }
        }
#pragma unroll
        for (int c = 0; c < CW; c++) {
            int chunk = tid + c * 256;
            int kr = chunk / (BN / 8);
            int nc = chunk % (BN / 8);
            rwh[c] = *(const uint4*)(Wgh + (size_t)(k0 + kr) * Nout + nc * 8);
            rwl[c] = *(const uint4*)(Wgl + (size_t)(k0 + kr) * Nout + nc * 8);
        }
    };
    auto store_tile = [&]() {
#pragma unroll
        for (int c = 0; c < CX; c++) {
            int chunk = tid + c * 256;
            int r = chunk >> 2;
            int ch = chunk & 3;
            *(uint4*)&Xhi[r * XS + ch * 8] = rxh[c];
            *(uint4*)&Xlo[r * XS + ch * 8] = rxl[c];
        }
#pragma unroll
        for (int c = 0; c < CW; c++) {
            int chunk = tid + c * 256;
            int kr = chunk / (BN / 8);
            int nc = chunk % (BN / 8);
            *(uint4*)&Whs[kr * WS + nc * 8] = rwh[c];
            *(uint4*)&Wls[kr * WS + nc * 8] = rwl[c];
        }
    };
    auto compute_tile = [&]() {
#pragma unroll
        for (int ks = 0; ks < BK / 16; ks++) {
            uint32_t ahi[MT][4];
            uint32_t alo[MT][4];
#pragma unroll
            for (int mt = 0; mt < MT; mt++) {
                int r = warp_m * 32 + mt * 16 + (lane & 15);
                int c = ks * 16 + (lane >> 4) * 8;
                uint32_t off = (uint32_t)(r * XS + c) * 2;
                ldsm_x4(xhi_b + off, ahi[mt][0], ahi[mt][1], ahi[mt][2], ahi[mt][3]);
                ldsm_x4(xlo_b + off, alo[mt][0], alo[mt][1], alo[mt][2], alo[mt][3]);
            }
            uint32_t bhi[NT][2];
            uint32_t blo[NT][2];
#pragma unroll
            for (int np = 0; np < NT / 2; np++) {
                int r = ks * 16 + (lane & 15);
                int c = warp_n * WN + np * 16 + (lane >> 4) * 8;
                uint32_t off = (uint32_t)(r * WS + c) * 2;
                ldsm_x4_t(whi_b + off, bhi[2 * np][0], bhi[2 * np][1],
                          bhi[2 * np + 1][0], bhi[2 * np + 1][1]);
                ldsm_x4_t(wlo_b + off, blo[2 * np][0], blo[2 * np][1],
                          blo[2 * np + 1][0], blo[2 * np + 1][1]);
            }
#pragma unroll
            for (int mt = 0; mt < MT; mt++)
#pragma unroll
                for (int nt = 0; nt < NT; nt++) {
                    mma_bf16(acc[mt][nt], ahi[mt], bhi[nt]);
                    mma_bf16(acc[mt][nt], ahi[mt], blo[nt]);
                    mma_bf16(acc[mt][nt], alo[mt], bhi[nt]);
                }
        }
    };

    load_tile(0);
    store_tile();
    __syncthreads();
    for (int it = 0;;) {
        bool has_next = (it + 1 < nIter);
        if (has_next) load_tile(it + 1);
        compute_tile();
        ++it;
        if (!has_next) break;
        __syncthreads();
        store_tile();
        __syncthreads();
    }

#pragma unroll
    for (int mt = 0; mt < MT; mt++) {
#pragma unroll
        for (int nt = 0; nt < NT; nt++) {
            int row = rowBase + warp_m * 32 + mt * 16 + (lane >> 2);
            int col = warp_n * WN + nt * 8 + (lane & 3) * 2;
            if (row < M)
                *(float2*)(out + (size_t)row * Nout + col) =
                    make_float2(acc[mt][nt][0], acc[mt][nt][1]);
            if (row + 8 < M)
                *(float2*)(out + (size_t)(row + 8) * Nout + col) =
                    make_float2(acc[mt][nt][2], acc[mt][nt][3]);
        }
    }
}

// ---------------------------------------------------------------------------
// Fused aggregation: res[d] = act( dinv[d]^2*H[d] + sum_e w[e]*H[src[e]] + b )
// One warp per node, 4-way unrolled gathers (MLP=4), no atomics.
// WSPLIT=1: write only bf16 hi/lo shadows (fp32 result is dead downstream).
// WSPLIT=0: write fp32 to `out`.
// ---------------------------------------------------------------------------
template <int F, int ACT, int WSPLIT>
__global__ void agg_fused(const float* __restrict__ H,
                          const int* __restrict__ rowstart,
                          const int* __restrict__ deg,
                          const int* __restrict__ csr_src,
                          const float* __restrict__ csr_w,
                          const float* __restrict__ dinv,
                          const float* __restrict__ bias,
                          float* __restrict__ out,
                          __nv_bfloat16* __restrict__ ohi,
                          __nv_bfloat16* __restrict__ olo, int M) {
    constexpr int V = F / 32;
    int warp = (blockIdx.x * blockDim.x + threadIdx.x) >> 5;
    if (warp >= M) return;
    int lane = threadIdx.x & 31;

    float acc[V];
    {
        float dv = dinv[warp];
        float s = dv * dv;
        if (V == 4) {
            float4 v = *(const float4*)(H + (size_t)warp * F + lane * 4);
            acc[0] = s * v.x; acc[1] = s * v.y; acc[2] = s * v.z; acc[3] = s * v.w;
        } else {
            float2 v = *(const float2*)(H + (size_t)warp * F + lane * 2);
            acc[0] = s * v.x; acc[1] = s * v.y;
        }
    }

    int beg = rowstart[warp];
    int n = deg[warp];
    int j = 0;
    for (; j + 4 <= n; j += 4) {
        int s0 = csr_src[beg + j + 0];
        int s1 = csr_src[beg + j + 1];
        int s2 = csr_src[beg + j + 2];
        int s3 = csr_src[beg + j + 3];
        float w0 = csr_w[beg + j + 0];
        float w1 = csr_w[beg + j + 1];
        float w2 = csr_w[beg + j + 2];
        float w3 = csr_w[beg + j + 3];
        if (V == 4) {
            float4 v0 = *(const float4*)(H + (size_t)s0 * F + lane * 4);
            float4 v1 = *(const float4*)(H + (size_t)s1 * F + lane * 4);
            float4 v2 = *(const float4*)(H + (size_t)s2 * F + lane * 4);
            float4 v3 = *(const float4*)(H + (size_t)s3 * F + lane * 4);
            acc[0] = fmaf(w0, v0.x, acc[0]); acc[1] = fmaf(w0, v0.y, acc[1]);
            acc[2] = fmaf(w0, v0.z, acc[2]); acc[3] = fmaf(w0, v0.w, acc[3]);
            acc[0] = fmaf(w1, v1.x, acc[0]); acc[1] = fmaf(w1, v1.y, acc[1]);
            acc[2] = fmaf(w1, v1.z, acc[2]); acc[3] = fmaf(w1, v1.w, acc[3]);
            acc[0] = fmaf(w2, v2.x, acc[0]); acc[1] = fmaf(w2, v2.y, acc[1]);
            acc[2] = fmaf(w2, v2.z, acc[2]); acc[3] = fmaf(w2, v2.w, acc[3]);
            acc[0] = fmaf(w3, v3.x, acc[0]); acc[1] = fmaf(w3, v3.y, acc[1]);
            acc[2] = fmaf(w3, v3.z, acc[2]); acc[3] = fmaf(w3, v3.w, acc[3]);
        } else {
            float2 v0 = *(const float2*)(H + (size_t)s0 * F + lane * 2);
            float2 v1 = *(const float2*)(H + (size_t)s1 * F + lane * 2);
            float2 v2 = *(const float2*)(H + (size_t)s2 * F + lane * 2);
            float2 v3 = *(const float2*)(H + (size_t)s3 * F + lane * 2);
            acc[0] = fmaf(w0, v0.x, acc[0]); acc[1] = fmaf(w0, v0.y, acc[1]);
            acc[0] = fmaf(w1, v1.x, acc[0]); acc[1] = fmaf(w1, v1.y, acc[1]);
            acc[0] = fmaf(w2, v2.x, acc[0]); acc[1] = fmaf(w2, v2.y, acc[1]);
            acc[0] = fmaf(w3, v3.x, acc[0]); acc[1] = fmaf(w3, v3.y, acc[1]);
        }
    }
    for (; j < n; j++) {
        int s0 = csr_src[beg + j];
        float w0 = csr_w[beg + j];
        if (V == 4) {
            float4 v0 = *(const float4*)(H + (size_t)s0 * F + lane * 4);
            acc[0] = fmaf(w0, v0.x, acc[0]); acc[1] = fmaf(w0, v0.y, acc[1]);
            acc[2] = fmaf(w0, v0.z, acc[2]); acc[3] = fmaf(w0, v0.w, acc[3]);
        } else {
            float2 v0 = *(const float2*)(H + (size_t)s0 * F + lane * 2);
            acc[0] = fmaf(w0, v0.x, acc[0]); acc[1] = fmaf(w0, v0.y, acc[1]);
        }
    }

    // bias + activation
    if (V == 4) {
        float4 b = *(const float4*)(bias + lane * 4);
        acc[0] += b.x; acc[1] += b.y; acc[2] += b.z; acc[3] += b.w;
    } else {
        float2 b = *(const float2*)(bias + lane * 2);
        acc[0] += b.x; acc[1] += b.y;
    }
    if (ACT) {
#pragma unroll
        for (int q = 0; q < V; q++) acc[q] = tanhf(acc[q]);
    }

    if (WSPLIT) {
        __nv_bfloat16 h[V], l[V];
#pragma unroll
        for (int q = 0; q < V; q++) split_bf16(acc[q], h[q], l[q]);
        if (V == 4) {
            size_t o = (size_t)warp * F + lane * 4;
            *(__nv_bfloat162*)(ohi + o)     = __nv_bfloat162(h[0], h[1]);
            *(__nv_bfloat162*)(ohi + o + 2) = __nv_bfloat162(h[2], h[3]);
            *(__nv_bfloat162*)(olo + o)     = __nv_bfloat162(l[0], l[1]);
            *(__nv_bfloat162*)(olo + o + 2) = __nv_bfloat162(l[2], l[3]);
        } else {
            size_t o = (size_t)warp * F + lane * 2;
            *(__nv_bfloat162*)(ohi + o) = __nv_bfloat162(h[0], h[1]);
            *(__nv_bfloat162*)(olo + o) = __nv_bfloat162(l[0], l[1]);
        }
    } else {
        if (V == 4)
            *(float4*)(out + (size_t)warp * F + lane * 4) =
                make_float4(acc[0], acc[1], acc[2], acc[3]);
        else
            *(float2*)(out + (size_t)warp * F + lane * 2) = make_float2(acc[0], acc[1]);
    }
}

// ---------------------------------------------------------------------------
// Host side
// ---------------------------------------------------------------------------
extern "C" void kernel_launch(void* const* d_in, const int* in_sizes, int n_in,
                              void* d_out, int out_size) {
    const float* feat = (const float*)d_in[0];
    const float* cond = (const float*)d_in[1];
    const int*   ei   = (const int*)d_in[2];
    const float* We1 = (const float*)d_in[3];
    const float* be1 = (const float*)d_in[4];
    const float* We2 = (const float*)d_in[5];
    const float* be2 = (const float*)d_in[6];
    const float* We3 = (const float*)d_in[7];
    const float* be3 = (const float*)d_in[8];
    const float* Wd1 = (const float*)d_in[9];
    const float* bd1 = (const float*)d_in[10];
    const float* Wd2 = (const float*)d_in[11];
    const float* bd2 = (const float*)d_in[12];
    const float* Wd3 = (const float*)d_in[13];
    const float* bd3 = (const float*)d_in[14];

    const int N = in_sizes[0] / 128;
    const int E = in_sizes[2] / 2;
    const int* src = ei;
    const int* dst = ei + E;
    float* out = (float*)d_out;

    float *dinv, *buf1, *csr_w;
    __nv_bfloat16 *fhi, *flo, *hhi, *hlo, *chi, *clo;
    __nv_bfloat16 *w1h, *w1l, *w2h, *w2l, *w3h, *w3l, *w4h, *w4l, *w5h, *w5l, *w6h, *w6l;
    int *deg, *rowstart, *cursor, *csr_src, *gcur;
    cudaGetSymbolAddress((void**)&dinv, g_dinv);
    cudaGetSymbolAddress((void**)&deg, g_deg);
    cudaGetSymbolAddress((void**)&rowstart, g_rowstart);
    cudaGetSymbolAddress((void**)&cursor, g_cursor);
    cudaGetSymbolAddress((void**)&csr_src, g_csr_src);
    cudaGetSymbolAddress((void**)&csr_w, g_csr_w);
    cudaGetSymbolAddress((void**)&buf1, g_buf1);
    cudaGetSymbolAddress((void**)&fhi, g_fhi);
    cudaGetSymbolAddress((void**)&flo, g_flo);
    cudaGetSymbolAddress((void**)&hhi, g_hhi);
    cudaGetSymbolAddress((void**)&hlo, g_hlo);
    cudaGetSymbolAddress((void**)&chi, g_chi);
    cudaGetSymbolAddress((void**)&clo, g_clo);
    cudaGetSymbolAddress((void**)&w1h, g_w1h); cudaGetSymbolAddress((void**)&w1l, g_w1l);
    cudaGetSymbolAddress((void**)&w2h, g_w2h); cudaGetSymbolAddress((void**)&w2l, g_w2l);
    cudaGetSymbolAddress((void**)&w3h, g_w3h); cudaGetSymbolAddress((void**)&w3l, g_w3l);
    cudaGetSymbolAddress((void**)&w4h, g_w4h); cudaGetSymbolAddress((void**)&w4l, g_w4l);
    cudaGetSymbolAddress((void**)&w5h, g_w5h); cudaGetSymbolAddress((void**)&w5l, g_w5l);
    cudaGetSymbolAddress((void**)&w6h, g_w6h); cudaGetSymbolAddress((void**)&w6l, g_w6l);
    cudaGetSymbolAddress((void**)&gcur, g_gcur);

    // total threads = feat + cond + all weights + deg/4 + 1 (gcur)
    const int splitThreads = N * 32 + N * 8 + WALLQ + N / 4 + 1;
    dim3 gB(1, cdiv(N, 128));
    const int aggBlocks = cdiv(N * 32, 256);

    // (1) all splits + deg/gcur reset
    split_all<<<cdiv(splitThreads, 256), 256>>>(
        feat, cond, We1, We2, We3, Wd1, Wd2, Wd3,
        fhi, flo, chi, clo, w1h, w1l, w2h, w2l, w3h, w3l,
        w4h, w4l, w5h, w5l, w6h, w6l, deg, gcur, N);
    // (2) degree count
    deg_count<<<cdiv(E, 256), 256>>>(dst, deg, E);
    // (3) dinv + slice assignment
    dinv_assign<<<cdiv(N, 256), 256>>>(deg, dinv, rowstart, cursor, gcur, N);
    // (4) encoder GEMM 1  <-- ncu capture slot
    gemm_bf16<128><<<gB, 256>>>(fhi, flo, 128, chi, clo, 32, w1h, w1l, buf1, N, 128);
    // (5) CSR fill
    csr_fill<<<cdiv(E, 256), 256>>>(src, dst, dinv, cursor, csr_src, csr_w, E);
    // (6) agg 1 (tanh)
    agg_fused<128, 1, 1><<<aggBlocks, 256>>>(buf1, rowstart, deg, csr_src, csr_w,
                                             dinv, be1, nullptr, hhi, hlo, N);
    // encoder layer 2
    gemm_bf16<128><<<gB, 256>>>(hhi, hlo, 128, nullptr, nullptr, 0, w2h, w2l, buf1, N, 128);
    agg_fused<128, 1, 1><<<aggBlocks, 256>>>(buf1, rowstart, deg, csr_src, csr_w,
                                             dinv, be2, nullptr, hhi, hlo, N);
    // encoder layer 3 (z, no act)
    gemm_bf16<64><<<gB, 256>>>(hhi, hlo, 128, nullptr, nullptr, 0, w3h, w3l, buf1, N, 64);
    agg_fused<64, 0, 1><<<aggBlocks, 256>>>(buf1, rowstart, deg, csr_src, csr_w,
                                            dinv, be3, nullptr, hhi, hlo, N);
    // decoder layer 1
    gemm_bf16<128><<<gB, 256>>>(hhi, hlo, 64, chi, clo, 32, w4h, w4l, buf1, N, 128);
    agg_fused<128, 1, 1><<<aggBlocks, 256>>>(buf1, rowstart, deg, csr_src, csr_w,
                                             dinv, bd1, nullptr, hhi, hlo, N);
    // decoder layer 2
    gemm_bf16<128><<<gB, 256>>>(hhi, hlo, 128, nullptr, nullptr, 0, w5h, w5l, buf1, N, 128);
    agg_fused<128, 1, 1><<<aggBlocks, 256>>>(buf1, rowstart, deg, csr_src, csr_w,
                                             dinv, bd2, nullptr, hhi, hlo, N);
    // decoder layer 3 -> d_out (fp32)
    gemm_bf16<128><<<gB, 256>>>(hhi, hlo, 128, nullptr, nullptr, 0, w6h, w6l, buf1, N, 128);
    agg_fused<128, 0, 0><<<aggBlocks, 256>>>(buf1, rowstart, deg, csr_src, csr_w,
                                             dinv, bd3, out, nullptr, nullptr, N);
}

// round 14
// speedup vs baseline: 1.2890x; 1.0959x over previous
#include <cuda_runtime.h>
#include <cuda_bf16.h>
#include <stdint.h>
#include <math.h>

// Problem constants (fixed by the dataset)
#define NN 100000
#define EE 1600000

// Scratch (allocation-free rule: static __device__ globals).
__device__ __align__(256) float          g_dinv[NN];
__device__ __align__(256) int            g_deg[NN];
__device__ __align__(256) int            g_rowstart[NN];
__device__ __align__(256) int            g_cursor[NN];
__device__ __align__(256) int            g_csr_src[EE];
__device__ __align__(256) float          g_csr_w[EE];
__device__ __align__(256) float          g_buf1[NN * 128];  // GEMM out (fp32)
__device__ __align__(256) __nv_bfloat16  g_fhi[NN * 128];   // feat hi
__device__ __align__(256) __nv_bfloat16  g_flo[NN * 128];   // feat lo
__device__ __align__(256) __nv_bfloat16  g_hhi[NN * 128];   // layer activation hi
__device__ __align__(256) __nv_bfloat16  g_hlo[NN * 128];   // layer activation lo
__device__ __align__(256) __nv_bfloat16  g_chi[NN * 32];    // cond hi
__device__ __align__(256) __nv_bfloat16  g_clo[NN * 32];    // cond lo
__device__ __align__(256) __nv_bfloat16  g_w1h[160 * 128], g_w1l[160 * 128];
__device__ __align__(256) __nv_bfloat16  g_w2h[128 * 128], g_w2l[128 * 128];
__device__ __align__(256) __nv_bfloat16  g_w3h[128 * 64],  g_w3l[128 * 64];
__device__ __align__(256) __nv_bfloat16  g_w4h[96 * 128],  g_w4l[96 * 128];
__device__ __align__(256) __nv_bfloat16  g_w5h[128 * 128], g_w5l[128 * 128];
__device__ __align__(256) __nv_bfloat16  g_w6h[128 * 128], g_w6l[128 * 128];
__device__ int g_gcur;

// float4-chunk counts of the 6 weight matrices (MUST match split_all's S-chain)
#define W1Q (160 * 128 / 4)
#define W2Q (128 * 128 / 4)
#define W3Q (128 * 64 / 4)
#define W4Q (96 * 128 / 4)
#define W5Q (128 * 128 / 4)
#define W6Q (128 * 128 / 4)
#define WALLQ (W1Q + W2Q + W3Q + W4Q + W5Q + W6Q)   // 22528

static inline int cdiv(int a, int b) { return (a + b - 1) / b; }

__device__ __forceinline__ void split_bf16(float x, __nv_bfloat16& h, __nv_bfloat16& l) {
    h = __float2bfloat16_rn(x);
    l = __float2bfloat16_rn(x - __bfloat162float(h));
}

__device__ __forceinline__ void split4(const float* __restrict__ src,
                                       __nv_bfloat16* __restrict__ hi,
                                       __nv_bfloat16* __restrict__ lo, int t) {
    float4 v = ((const float4*)src)[t];
    __nv_bfloat16 h0, h1, h2, h3, l0, l1, l2, l3;
    split_bf16(v.x, h0, l0); split_bf16(v.y, h1, l1);
    split_bf16(v.z, h2, l2); split_bf16(v.w, h3, l3);
    ((__nv_bfloat162*)hi)[t * 2 + 0] = __nv_bfloat162(h0, h1);
    ((__nv_bfloat162*)hi)[t * 2 + 1] = __nv_bfloat162(h2, h3);
    ((__nv_bfloat162*)lo)[t * 2 + 0] = __nv_bfloat162(l0, l1);
    ((__nv_bfloat162*)lo)[t * 2 + 1] = __nv_bfloat162(l2, l3);
}

// ---------------------------------------------------------------------------
// One kernel: split feat/cond/all-6-weights to bf16 hi/lo + zero deg & gcur.
// ---------------------------------------------------------------------------
__global__ void split_all(const float* feat, const float* cond,
                          const float* We1, const float* We2, const float* We3,
                          const float* Wd1, const float* Wd2, const float* Wd3,
                          __nv_bfloat16* fhi, __nv_bfloat16* flo,
                          __nv_bfloat16* chi, __nv_bfloat16* clo,
                          __nv_bfloat16* w1h, __nv_bfloat16* w1l,
                          __nv_bfloat16* w2h, __nv_bfloat16* w2l,
                          __nv_bfloat16* w3h, __nv_bfloat16* w3l,
                          __nv_bfloat16* w4h, __nv_bfloat16* w4l,
                          __nv_bfloat16* w5h, __nv_bfloat16* w5l,
                          __nv_bfloat16* w6h, __nv_bfloat16* w6l,
                          int* deg, int* gcur, int N) {
    const int S0 = N * 32;          // feat (N*128/4)
    const int S1 = S0 + N * 8;      // cond (N*32/4)
    const int S2 = S1 + W1Q;
    const int S3 = S2 + W2Q;
    const int S4 = S3 + W3Q;
    const int S5 = S4 + W4Q;
    const int S6 = S5 + W5Q;
    const int S7 = S6 + W6Q;
    const int S8 = S7 + N / 4;      // deg zero (int4)
    int t = blockIdx.x * blockDim.x + threadIdx.x;
    if (t < S0)      split4(feat, fhi, flo, t);
    else if (t < S1) split4(cond, chi, clo, t - S0);
    else if (t < S2) split4(We1, w1h, w1l, t - S1);
    else if (t < S3) split4(We2, w2h, w2l, t - S2);
    else if (t < S4) split4(We3, w3h, w3l, t - S3);
    else if (t < S5) split4(Wd1, w4h, w4l, t - S4);
    else if (t < S6) split4(Wd2, w5h, w5l, t - S5);
    else if (t < S7) split4(Wd3, w6h, w6l, t - S6);
    else if (t < S8) ((int4*)deg)[t - S7] = make_int4(0, 0, 0, 0);
    else if (t == S8) *gcur = 0;
}

// ---------------------------------------------------------------------------
// CSR construction (edge_index is int32)
// ---------------------------------------------------------------------------
__global__ void deg_count(const int* __restrict__ dst, int* __restrict__ deg, int E) {
    int i = blockIdx.x * blockDim.x + threadIdx.x;
    if (i < E) atomicAdd(&deg[dst[i]], 1);
}

__global__ void dinv_assign(const int* __restrict__ deg, float* __restrict__ dinv,
                            int* __restrict__ rowstart, int* __restrict__ cursor,
                            int* gcur, int n) {
    int i = blockIdx.x * blockDim.x + threadIdx.x;
    int lane = threadIdx.x & 31;
    int d = (i < n) ? deg[i] : 0;
    if (i < n) dinv[i] = rsqrtf((float)d + 1.0f);
    int incl = d;
#pragma unroll
    for (int o = 1; o < 32; o <<= 1) {
        int v = __shfl_up_sync(0xFFFFFFFFu, incl, o);
        if (lane >= o) incl += v;
    }
    int total = __shfl_sync(0xFFFFFFFFu, incl, 31);
    int base = 0;
    if (lane == 31) base = atomicAdd(gcur, total);
    base = __shfl_sync(0xFFFFFFFFu, base, 31);
    int excl = incl - d;
    if (i < n) {
        rowstart[i] = base + excl;
        cursor[i]   = base + excl;
    }
}

__global__ void csr_fill(const int* __restrict__ src, const int* __restrict__ dst,
                         const float* __restrict__ dinv,
                         int* __restrict__ cursor,
                         int* __restrict__ csr_src, float* __restrict__ csr_w, int E) {
    int i = blockIdx.x * blockDim.x + threadIdx.x;
    if (i >= E) return;
    int s = src[i];
    int d = dst[i];
    int pos = atomicAdd(&cursor[d], 1);
    csr_src[pos] = s;
    csr_w[pos] = dinv[s] * dinv[d];
}

// ---------------------------------------------------------------------------
// bf16-split tensor-core GEMM, cp.async double-buffered, 2 CTAs/SM.
// out = concat(xA,xB) @ W via A_hi*B_hi + A_hi*B_lo + A_lo*B_hi, fp32 accum.
// BM=128, BK=32, 256 threads (8 warps, 4x2). Dynamic smem, 2 stages.
// ---------------------------------------------------------------------------
__device__ __forceinline__ void ldsm_x4(uint32_t a, uint32_t& r0, uint32_t& r1,
                                        uint32_t& r2, uint32_t& r3) {
    asm volatile("ldmatrix.sync.aligned.m8n8.x4.shared.b16 {%0,%1,%2,%3}, [%4];"
                 : "=r"(r0), "=r"(r1), "=r"(r2), "=r"(r3) : "r"(a));
}
__device__ __forceinline__ void ldsm_x4_t(uint32_t a, uint32_t& r0, uint32_t& r1,
                                          uint32_t& r2, uint32_t& r3) {
    asm volatile("ldmatrix.sync.aligned.m8n8.x4.trans.shared.b16 {%0,%1,%2,%3}, [%4];"
                 : "=r"(r0), "=r"(r1), "=r"(r2), "=r"(r3) : "r"(a));
}
__device__ __forceinline__ void mma_bf16(float* c, const uint32_t* a, const uint32_t* b) {
    asm volatile(
        "mma.sync.aligned.m16n8k16.row.col.f32.bf16.bf16.f32 "
        "{%0,%1,%2,%3}, {%4,%5,%6,%7}, {%8,%9}, {%0,%1,%2,%3};"
        : "+f"(c[0]), "+f"(c[1]), "+f"(c[2]), "+f"(c[3])
        : "r"(a[0]), "r"(a[1]), "r"(a[2]), "r"(a[3]), "r"(b[0]), "r"(b[1]));
}
__device__ __forceinline__ void cp16(uint32_t dst, const void* src, bool valid) {
    int sz = valid ? 16 : 0;
    asm volatile("cp.async.cg.shared.global [%0], [%1], 16, %2;"
                 :: "r"(dst), "l"(src), "r"(sz));
}
__device__ __forceinline__ void cp_commit() {
    asm volatile("cp.async.commit_group;");
}

template <int BN>
__global__ __launch_bounds__(256, 2)
void gemm_bf16(const __nv_bfloat16* __restrict__ xAhi,
               const __nv_bfloat16* __restrict__ xAlo, int KA,
               const __nv_bfloat16* __restrict__ xBhi,
               const __nv_bfloat16* __restrict__ xBlo, int KB,
               const __nv_bfloat16* __restrict__ Wgh,
               const __nv_bfloat16* __restrict__ Wgl,
               float* __restrict__ out, int M, int Nout) {
    constexpr int BM = 128, BK = 32;
    constexpr int XS = BK + 8;                 // 40 bf16 / row
    constexpr int WS = BN + 8;
    constexpr int WN = BN / 2;
    constexpr int NT = WN / 8;
    constexpr int MT = 2;
    constexpr int XSZ = BM * XS;               // elems
    constexpr int WSZ = BK * WS;
    constexpr int STAGE = 2 * XSZ + 2 * WSZ;   // Xhi,Xlo,Whs,Wls
    constexpr int CW = (BK * BN / 8) / 256;    // W 16B chunks / thread (2 or 1)

    extern __shared__ char dynsmem[];
    __nv_bfloat16* sm = (__nv_bfloat16*)dynsmem;

    const int K = KA + KB;
    const int nIter = K / BK;
    const int tid = threadIdx.x;
    const int lane = tid & 31;
    const int warp = tid >> 5;
    const int warp_m = warp >> 1;
    const int warp_n = warp & 1;
    const int rowBase = blockIdx.y * BM;

    float acc[MT][NT][4];
#pragma unroll
    for (int i = 0; i < MT; i++)
#pragma unroll
        for (int j = 0; j < NT; j++)
#pragma unroll
            for (int q = 0; q < 4; q++) acc[i][j][q] = 0.0f;

    const uint32_t smb = (uint32_t)__cvta_generic_to_shared(sm);

    // issue cp.asyncs for tile `it` into stage `st`
    auto issue_tile = [&](int it, int st) {
        int k0 = it * BK;
        uint32_t base = smb + (uint32_t)(st * STAGE) * 2;
        uint32_t xhi = base, xlo = base + XSZ * 2;
        uint32_t whs = base + 2 * XSZ * 2, wls = base + (2 * XSZ + WSZ) * 2;
        // X: 512 chunks each for hi/lo; thread t covers chunks {t, t+256}
#pragma unroll
        for (int c = 0; c < 2; c++) {
            int chunk = tid + c * 256;
            int r = chunk >> 2;                // row 0..127
            int ch = chunk & 3;                // 16B chunk along K
            int gr = rowBase + r;
            int kk = k0 + ch * 8;
            bool valid = gr < M;
            uint32_t doff = (uint32_t)(r * XS + ch * 8) * 2;
            const __nv_bfloat16 *ph, *pl;
            if (kk < KA) {
                ph = xAhi + (size_t)gr * KA + kk;
                pl = xAlo + (size_t)gr * KA + kk;
            } else {
                ph = xBhi + (size_t)gr * KB + (kk - KA);
                pl = xBlo + (size_t)gr * KB + (kk - KA);
            }
            if (!valid) { ph = xAhi; pl = xAlo; }   // safe dummy address, sz=0
            cp16(xhi + doff, ph, valid);
            cp16(xlo + doff, pl, valid);
        }
        // W: BK*BN/8 chunks each hi/lo
#pragma unroll
        for (int c = 0; c < CW; c++) {
            int chunk = tid + c * 256;
            int kr = chunk / (BN / 8);
            int nc = chunk % (BN / 8);
            uint32_t doff = (uint32_t)(kr * WS + nc * 8) * 2;
            cp16(whs + doff, Wgh + (size_t)(k0 + kr) * Nout + nc * 8, true);
            cp16(wls + doff, Wgl + (size_t)(k0 + kr) * Nout + nc * 8, true);
        }
        cp_commit();
    };

    auto compute_tile = [&](int st) {
        uint32_t base = smb + (uint32_t)(st * STAGE) * 2;
        uint32_t xhi = base, xlo = base + XSZ * 2;
        uint32_t whs = base + 2 * XSZ * 2, wls = base + (2 * XSZ + WSZ) * 2;
#pragma unroll
        for (int ks = 0; ks < BK / 16; ks++) {
            uint32_t ahi[MT][4];
            uint32_t alo[MT][4];
#pragma unroll
            for (int mt = 0; mt < MT; mt++) {
                int r = warp_m * 32 + mt * 16 + (lane & 15);
                int c = ks * 16 + (lane >> 4) * 8;
                uint32_t off = (uint32_t)(r * XS + c) * 2;
                ldsm_x4(xhi + off, ahi[mt][0], ahi[mt][1], ahi[mt][2], ahi[mt][3]);
                ldsm_x4(xlo + off, alo[mt][0], alo[mt][1], alo[mt][2], alo[mt][3]);
            }
            uint32_t bhi[NT][2];
            uint32_t blo[NT][2];
#pragma unroll
            for (int np = 0; np < NT / 2; np++) {
                int r = ks * 16 + (lane & 15);
                int c = warp_n * WN + np * 16 + (lane >> 4) * 8;
                uint32_t off = (uint32_t)(r * WS + c) * 2;
                ldsm_x4_t(whs + off, bhi[2 * np][0], bhi[2 * np][1],
                          bhi[2 * np + 1][0], bhi[2 * np + 1][1]);
                ldsm_x4_t(wls + off, blo[2 * np][0], blo[2 * np][1],
                          blo[2 * np + 1][0], blo[2 * np + 1][1]);
            }
#pragma unroll
            for (int mt = 0; mt < MT; mt++)
#pragma unroll
                for (int nt = 0; nt < NT; nt++) {
                    mma_bf16(acc[mt][nt], ahi[mt], bhi[nt]);
                    mma_bf16(acc[mt][nt], ahi[mt], blo[nt]);
                    mma_bf16(acc[mt][nt], alo[mt], bhi[nt]);
                }
        }
    };

    // ---- double-buffered mainloop ----
    issue_tile(0, 0);
    for (int it = 0; it < nIter; it++) {
        if (it + 1 < nIter) {
            issue_tile(it + 1, (it + 1) & 1);
            asm volatile("cp.async.wait_group 1;");
        } else {
            asm volatile("cp.async.wait_group 0;");
        }
        __syncthreads();            // tile `it` visible to all warps
        compute_tile(it & 1);
        __syncthreads();            // done reading before stage reuse
    }

    // ---- store fp32 ----
#pragma unroll
    for (int mt = 0; mt < MT; mt++) {
#pragma unroll
        for (int nt = 0; nt < NT; nt++) {
            int row = rowBase + warp_m * 32 + mt * 16 + (lane >> 2);
            int col = warp_n * WN + nt * 8 + (lane & 3) * 2;
            if (row < M)
                *(float2*)(out + (size_t)row * Nout + col) =
                    make_float2(acc[mt][nt][0], acc[mt][nt][1]);
            if (row + 8 < M)
                *(float2*)(out + (size_t)(row + 8) * Nout + col) =
                    make_float2(acc[mt][nt][2], acc[mt][nt][3]);
        }
    }
}

// dynamic smem sizes (bytes) for the two instantiations
#define GEMM_SMEM(BN) (2 * (2 * 128 * 40 + 2 * 32 * ((BN) + 8)) * 2)

// ---------------------------------------------------------------------------
// Fused aggregation: res[d] = act( dinv[d]^2*H[d] + sum_e w[e]*H[src[e]] + b )
// One warp per node, 4-way unrolled gathers, no atomics.
// ---------------------------------------------------------------------------
template <int F, int ACT, int WSPLIT>
__global__ void agg_fused(const float* __restrict__ H,
                          const int* __restrict__ rowstart,
                          const int* __restrict__ deg,
                          const int* __restrict__ csr_src,
                          const float* __restrict__ csr_w,
                          const float* __restrict__ dinv,
                          const float* __restrict__ bias,
                          float* __restrict__ out,
                          __nv_bfloat16* __restrict__ ohi,
                          __nv_bfloat16* __restrict__ olo, int M) {
    constexpr int V = F / 32;
    int warp = (blockIdx.x * blockDim.x + threadIdx.x) >> 5;
    if (warp >= M) return;
    int lane = threadIdx.x & 31;

    float acc[V];
    {
        float dv = dinv[warp];
        float s = dv * dv;
        if (V == 4) {
            float4 v = *(const float4*)(H + (size_t)warp * F + lane * 4);
            acc[0] = s * v.x; acc[1] = s * v.y; acc[2] = s * v.z; acc[3] = s * v.w;
        } else {
            float2 v = *(const float2*)(H + (size_t)warp * F + lane * 2);
            acc[0] = s * v.x; acc[1] = s * v.y;
        }
    }

    int beg = rowstart[warp];
    int n = deg[warp];
    int j = 0;
    for (; j + 4 <= n; j += 4) {
        int s0 = csr_src[beg + j + 0];
        int s1 = csr_src[beg + j + 1];
        int s2 = csr_src[beg + j + 2];
        int s3 = csr_src[beg + j + 3];
        float w0 = csr_w[beg + j + 0];
        float w1 = csr_w[beg + j + 1];
        float w2 = csr_w[beg + j + 2];
        float w3 = csr_w[beg + j + 3];
        if (V == 4) {
            float4 v0 = *(const float4*)(H + (size_t)s0 * F + lane * 4);
            float4 v1 = *(const float4*)(H + (size_t)s1 * F + lane * 4);
            float4 v2 = *(const float4*)(H + (size_t)s2 * F + lane * 4);
            float4 v3 = *(const float4*)(H + (size_t)s3 * F + lane * 4);
            acc[0] = fmaf(w0, v0.x, acc[0]); acc[1] = fmaf(w0, v0.y, acc[1]);
            acc[2] = fmaf(w0, v0.z, acc[2]); acc[3] = fmaf(w0, v0.w, acc[3]);
            acc[0] = fmaf(w1, v1.x, acc[0]); acc[1] = fmaf(w1, v1.y, acc[1]);
            acc[2] = fmaf(w1, v1.z, acc[2]); acc[3] = fmaf(w1, v1.w, acc[3]);
            acc[0] = fmaf(w2, v2.x, acc[0]); acc[1] = fmaf(w2, v2.y, acc[1]);
            acc[2] = fmaf(w2, v2.z, acc[2]); acc[3] = fmaf(w2, v2.w, acc[3]);
            acc[0] = fmaf(w3, v3.x, acc[0]); acc[1] = fmaf(w3, v3.y, acc[1]);
            acc[2] = fmaf(w3, v3.z, acc[2]); acc[3] = fmaf(w3, v3.w, acc[3]);
        } else {
            float2 v0 = *(const float2*)(H + (size_t)s0 * F + lane * 2);
            float2 v1 = *(const float2*)(H + (size_t)s1 * F + lane * 2);
            float2 v2 = *(const float2*)(H + (size_t)s2 * F + lane * 2);
            float2 v3 = *(const float2*)(H + (size_t)s3 * F + lane * 2);
            acc[0] = fmaf(w0, v0.x, acc[0]); acc[1] = fmaf(w0, v0.y, acc[1]);
            acc[0] = fmaf(w1, v1.x, acc[0]); acc[1] = fmaf(w1, v1.y, acc[1]);
            acc[0] = fmaf(w2, v2.x, acc[0]); acc[1] = fmaf(w2, v2.y, acc[1]);
            acc[0] = fmaf(w3, v3.x, acc[0]); acc[1] = fmaf(w3, v3.y, acc[1]);
        }
    }
    for (; j < n; j++) {
        int s0 = csr_src[beg + j];
        float w0 = csr_w[beg + j];
        if (V == 4) {
            float4 v0 = *(const float4*)(H + (size_t)s0 * F + lane * 4);
            acc[0] = fmaf(w0, v0.x, acc[0]); acc[1] = fmaf(w0, v0.y, acc[1]);
            acc[2] = fmaf(w0, v0.z, acc[2]); acc[3] = fmaf(w0, v0.w, acc[3]);
        } else {
            float2 v0 = *(const float2*)(H + (size_t)s0 * F + lane * 2);
            acc[0] = fmaf(w0, v0.x, acc[0]); acc[1] = fmaf(w0, v0.y, acc[1]);
        }
    }

    if (V == 4) {
        float4 b = *(const float4*)(bias + lane * 4);
        acc[0] += b.x; acc[1] += b.y; acc[2] += b.z; acc[3] += b.w;
    } else {
        float2 b = *(const float2*)(bias + lane * 2);
        acc[0] += b.x; acc[1] += b.y;
    }
    if (ACT) {
#pragma unroll
        for (int q = 0; q < V; q++) acc[q] = tanhf(acc[q]);
    }

    if (WSPLIT) {
        __nv_bfloat16 h[V], l[V];
#pragma unroll
        for (int q = 0; q < V; q++) split_bf16(acc[q], h[q], l[q]);
        if (V == 4) {
            size_t o = (size_t)warp * F + lane * 4;
            *(__nv_bfloat162*)(ohi + o)     = __nv_bfloat162(h[0], h[1]);
            *(__nv_bfloat162*)(ohi + o + 2) = __nv_bfloat162(h[2], h[3]);
            *(__nv_bfloat162*)(olo + o)     = __nv_bfloat162(l[0], l[1]);
            *(__nv_bfloat162*)(olo + o + 2) = __nv_bfloat162(l[2], l[3]);
        } else {
            size_t o = (size_t)warp * F + lane * 2;
            *(__nv_bfloat162*)(ohi + o) = __nv_bfloat162(h[0], h[1]);
            *(__nv_bfloat162*)(olo + o) = __nv_bfloat162(l[0], l[1]);
        }
    } else {
        if (V == 4)
            *(float4*)(out + (size_t)warp * F + lane * 4) =
                make_float4(acc[0], acc[1], acc[2], acc[3]);
        else
            *(float2*)(out + (size_t)warp * F + lane * 2) = make_float2(acc[0], acc[1]);
    }
}

// ---------------------------------------------------------------------------
// Host side
// ---------------------------------------------------------------------------
extern "C" void kernel_launch(void* const* d_in, const int* in_sizes, int n_in,
                              void* d_out, int out_size) {
    const float* feat = (const float*)d_in[0];
    const float* cond = (const float*)d_in[1];
    const int*   ei   = (const int*)d_in[2];
    const float* We1 = (const float*)d_in[3];
    const float* be1 = (const float*)d_in[4];
    const float* We2 = (const float*)d_in[5];
    const float* be2 = (const float*)d_in[6];
    const float* We3 = (const float*)d_in[7];
    const float* be3 = (const float*)d_in[8];
    const float* Wd1 = (const float*)d_in[9];
    const float* bd1 = (const float*)d_in[10];
    const float* Wd2 = (const float*)d_in[11];
    const float* bd2 = (const float*)d_in[12];
    const float* Wd3 = (const float*)d_in[13];
    const float* bd3 = (const float*)d_in[14];

    const int N = in_sizes[0] / 128;
    const int E = in_sizes[2] / 2;
    const int* src = ei;
    const int* dst = ei + E;
    float* out = (float*)d_out;

    float *dinv, *buf1, *csr_w;
    __nv_bfloat16 *fhi, *flo, *hhi, *hlo, *chi, *clo;
    __nv_bfloat16 *w1h, *w1l, *w2h, *w2l, *w3h, *w3l, *w4h, *w4l, *w5h, *w5l, *w6h, *w6l;
    int *deg, *rowstart, *cursor, *csr_src, *gcur;
    cudaGetSymbolAddress((void**)&dinv, g_dinv);
    cudaGetSymbolAddress((void**)&deg, g_deg);
    cudaGetSymbolAddress((void**)&rowstart, g_rowstart);
    cudaGetSymbolAddress((void**)&cursor, g_cursor);
    cudaGetSymbolAddress((void**)&csr_src, g_csr_src);
    cudaGetSymbolAddress((void**)&csr_w, g_csr_w);
    cudaGetSymbolAddress((void**)&buf1, g_buf1);
    cudaGetSymbolAddress((void**)&fhi, g_fhi);
    cudaGetSymbolAddress((void**)&flo, g_flo);
    cudaGetSymbolAddress((void**)&hhi, g_hhi);
    cudaGetSymbolAddress((void**)&hlo, g_hlo);
    cudaGetSymbolAddress((void**)&chi, g_chi);
    cudaGetSymbolAddress((void**)&clo, g_clo);
    cudaGetSymbolAddress((void**)&w1h, g_w1h); cudaGetSymbolAddress((void**)&w1l, g_w1l);
    cudaGetSymbolAddress((void**)&w2h, g_w2h); cudaGetSymbolAddress((void**)&w2l, g_w2l);
    cudaGetSymbolAddress((void**)&w3h, g_w3h); cudaGetSymbolAddress((void**)&w3l, g_w3l);
    cudaGetSymbolAddress((void**)&w4h, g_w4h); cudaGetSymbolAddress((void**)&w4l, g_w4l);
    cudaGetSymbolAddress((void**)&w5h, g_w5h); cudaGetSymbolAddress((void**)&w5l, g_w5l);
    cudaGetSymbolAddress((void**)&w6h, g_w6h); cudaGetSymbolAddress((void**)&w6l, g_w6l);
    cudaGetSymbolAddress((void**)&gcur, g_gcur);

    // raise dynamic smem limits (idempotent; host-side attribute set, no alloc)
    static bool attr_done = false;
    if (!attr_done) {
        cudaFuncSetAttribute(gemm_bf16<128>, cudaFuncAttributeMaxDynamicSharedMemorySize,
                             GEMM_SMEM(128));
        cudaFuncSetAttribute(gemm_bf16<64>, cudaFuncAttributeMaxDynamicSharedMemorySize,
                             GEMM_SMEM(64));
        attr_done = true;
    }

    const int splitThreads = N * 32 + N * 8 + WALLQ + N / 4 + 1;
    dim3 gB(1, cdiv(N, 128));
    const int aggBlocks = cdiv(N * 32, 256);

    // (1) all splits + deg/gcur reset
    split_all<<<cdiv(splitThreads, 256), 256>>>(
        feat, cond, We1, We2, We3, Wd1, Wd2, Wd3,
        fhi, flo, chi, clo, w1h, w1l, w2h, w2l, w3h, w3l,
        w4h, w4l, w5h, w5l, w6h, w6l, deg, gcur, N);
    // (2) degree count
    deg_count<<<cdiv(E, 256), 256>>>(dst, deg, E);
    // (3) dinv + slice assignment
    dinv_assign<<<cdiv(N, 256), 256>>>(deg, dinv, rowstart, cursor, gcur, N);
    // (4) encoder GEMM 1  <-- ncu capture slot
    gemm_bf16<128><<<gB, 256, GEMM_SMEM(128)>>>(fhi, flo, 128, chi, clo, 32,
                                                w1h, w1l, buf1, N, 128);
    // (5) CSR fill
    csr_fill<<<cdiv(E, 256), 256>>>(src, dst, dinv, cursor, csr_src, csr_w, E);
    // (6) agg 1 (tanh)
    agg_fused<128, 1, 1><<<aggBlocks, 256>>>(buf1, rowstart, deg, csr_src, csr_w,
                                             dinv, be1, nullptr, hhi, hlo, N);
    // encoder layer 2
    gemm_bf16<128><<<gB, 256, GEMM_SMEM(128)>>>(hhi, hlo, 128, nullptr, nullptr, 0,
                                                w2h, w2l, buf1, N, 128);
    agg_fused<128, 1, 1><<<aggBlocks, 256>>>(buf1, rowstart, deg, csr_src, csr_w,
                                             dinv, be2, nullptr, hhi, hlo, N);
    // encoder layer 3 (z, no act)
    gemm_bf16<64><<<gB, 256, GEMM_SMEM(64)>>>(hhi, hlo, 128, nullptr, nullptr, 0,
                                              w3h, w3l, buf1, N, 64);
    agg_fused<64, 0, 1><<<aggBlocks, 256>>>(buf1, rowstart, deg, csr_src, csr_w,
                                            dinv, be3, nullptr, hhi, hlo, N);
    // decoder layer 1
    gemm_bf16<128><<<gB, 256, GEMM_SMEM(128)>>>(hhi, hlo, 64, chi, clo, 32,
                                                w4h, w4l, buf1, N, 128);
    agg_fused<128, 1, 1><<<aggBlocks, 256>>>(buf1, rowstart, deg, csr_src, csr_w,
                                             dinv, bd1, nullptr, hhi, hlo, N);
    // decoder layer 2
    gemm_bf16<128><<<gB, 256, GEMM_SMEM(128)>>>(hhi, hlo, 128, nullptr, nullptr, 0,
                                                w5h, w5l, buf1, N, 128);
    agg_fused<128, 1, 1><<<aggBlocks, 256>>>(buf1, rowstart, deg, csr_src, csr_w,
                                             dinv, bd2, nullptr, hhi, hlo, N);
    // decoder layer 3 -> d_out (fp32)
    gemm_bf16<128><<<gB, 256, GEMM_SMEM(128)>>>(hhi, hlo, 128, nullptr, nullptr, 0,
                                                w6h, w6l, buf1, N, 128);
    agg_fused<128, 0, 0><<<aggBlocks, 256>>>(buf1, rowstart, deg, csr_src, csr_w,
                                             dinv, bd3, out, nullptr, nullptr, N);
}